// round 1
// baseline (speedup 1.0000x reference)
#include <cuda_runtime.h>
#include <cstdint>

#define Bb 2
#define Ss 2048
#define Dd 1024
#define Hh 16
#define DKk 64
#define Mm (Bb*Ss)

// Scratch (allocation-free rule: __device__ globals)
__device__ float g_Qh[Bb*Hh*Ss*DKk];
__device__ float g_Kh[Bb*Hh*Ss*DKk];
__device__ float g_Vh[Bb*Hh*Ss*DKk];
__device__ float g_ctx[Bb*Ss*Dd];

__device__ __forceinline__ unsigned f2tf(float x){
    unsigned u; asm("cvt.rna.tf32.f32 %0, %1;" : "=r"(u) : "f"(x)); return u;
}
__device__ __forceinline__ float f2tff(float x){ return __uint_as_float(f2tf(x)); }

__device__ __forceinline__ void mma8(float* c,
    unsigned a0, unsigned a1, unsigned a2, unsigned a3,
    unsigned b0, unsigned b1)
{
    asm volatile(
      "mma.sync.aligned.m16n8k8.row.col.f32.tf32.tf32.f32 "
      "{%0,%1,%2,%3},{%4,%5,%6,%7},{%8,%9},{%0,%1,%2,%3};\n"
      : "+f"(c[0]), "+f"(c[1]), "+f"(c[2]), "+f"(c[3])
      : "r"(a0), "r"(a1), "r"(a2), "r"(a3), "r"(b0), "r"(b1));
}

// head-layout index for Qh/Kh/Vh: m=(b*S+s), n=(h*64+dk) -> [b][h][s][dk]
__device__ __forceinline__ size_t hidx(int m, int n){
    int b = m >> 11;          // / 2048
    int s = m & 2047;
    int h = n >> 6;
    int dk = n & 63;
    return (((size_t)b*Hh + h)*Ss + s)*DKk + dk;
}

// ---------------------------------------------------------------------------
// GEMM: C[M=4096,N=1024] = X @ W^T + bias.  X row-major [M,1024], W row-major
// [N,1024] (both K-major -> mma row.col directly).
// mode 0/1/2: write head-layout into g_Qh/g_Kh/g_Vh. mode 3: X=g_ctx, write
// row-major [M,N] to outp.
// Block 128x128, BK=32, 8 warps (2m x 4n), warp tile 64x32.
// ---------------------------------------------------------------------------
#define PST 36   // smem row stride (floats): (4r+c) mod 32 conflict-free

__global__ void __launch_bounds__(256)
gemm_proj(const float* __restrict__ X, const float* __restrict__ W,
          const float* __restrict__ bias, float* __restrict__ outp, int mode)
{
    __shared__ float As[128*PST];
    __shared__ float Bs[128*PST];

    const float* Xp = (mode == 3) ? g_ctx : X;
    float* op = (mode == 0) ? g_Qh : (mode == 1) ? g_Kh : (mode == 2) ? g_Vh : outp;

    const int tid = threadIdx.x;
    const int lane = tid & 31, w = tid >> 5;
    const int wm = w >> 2, wn = w & 3;          // 2 x 4 warp grid
    const int g = lane >> 2, tg = lane & 3;
    const int by = blockIdx.y, bx = blockIdx.x;
    const int lr = tid >> 3, lc = (tid & 7) * 4;

    float acc[4][4][4];
    #pragma unroll
    for (int mt = 0; mt < 4; mt++)
        #pragma unroll
        for (int nt = 0; nt < 4; nt++)
            #pragma unroll
            for (int j = 0; j < 4; j++) acc[mt][nt][j] = 0.f;

    const float* xblk = Xp + (size_t)(by*128) * Dd;
    const float* wblk = W  + (size_t)(bx*128) * Dd;

    for (int kt = 0; kt < Dd/32; kt++) {
        float4 xa[4], wa[4];
        #pragma unroll
        for (int i = 0; i < 4; i++) {
            xa[i] = *(const float4*)(xblk + (size_t)(lr + 32*i)*Dd + kt*32 + lc);
            wa[i] = *(const float4*)(wblk + (size_t)(lr + 32*i)*Dd + kt*32 + lc);
        }
        __syncthreads();
        #pragma unroll
        for (int i = 0; i < 4; i++) {
            int r = lr + 32*i;
            As[r*PST + lc + 0] = f2tff(xa[i].x);
            As[r*PST + lc + 1] = f2tff(xa[i].y);
            As[r*PST + lc + 2] = f2tff(xa[i].z);
            As[r*PST + lc + 3] = f2tff(xa[i].w);
            Bs[r*PST + lc + 0] = f2tff(wa[i].x);
            Bs[r*PST + lc + 1] = f2tff(wa[i].y);
            Bs[r*PST + lc + 2] = f2tff(wa[i].z);
            Bs[r*PST + lc + 3] = f2tff(wa[i].w);
        }
        __syncthreads();

        #pragma unroll
        for (int k8 = 0; k8 < 32; k8 += 8) {
            unsigned a[4][4], bfr[4][2];
            #pragma unroll
            for (int mt = 0; mt < 4; mt++) {
                int r = wm*64 + mt*16 + g;
                a[mt][0] = __float_as_uint(As[r*PST     + k8 + tg]);
                a[mt][1] = __float_as_uint(As[(r+8)*PST + k8 + tg]);
                a[mt][2] = __float_as_uint(As[r*PST     + k8 + tg + 4]);
                a[mt][3] = __float_as_uint(As[(r+8)*PST + k8 + tg + 4]);
            }
            #pragma unroll
            for (int nt = 0; nt < 4; nt++) {
                int n = wn*32 + nt*8 + g;
                bfr[nt][0] = __float_as_uint(Bs[n*PST + k8 + tg]);
                bfr[nt][1] = __float_as_uint(Bs[n*PST + k8 + tg + 4]);
            }
            #pragma unroll
            for (int mt = 0; mt < 4; mt++)
                #pragma unroll
                for (int nt = 0; nt < 4; nt++)
                    mma8(acc[mt][nt], a[mt][0], a[mt][1], a[mt][2], a[mt][3],
                         bfr[nt][0], bfr[nt][1]);
        }
    }

    // epilogue
    #pragma unroll
    for (int mt = 0; mt < 4; mt++) {
        int m0 = by*128 + wm*64 + mt*16 + g;
        #pragma unroll
        for (int nt = 0; nt < 4; nt++) {
            int n0 = bx*128 + wn*32 + nt*8 + tg*2;
            float bv0 = bias[n0], bv1 = bias[n0 + 1];
            if (mode < 3) {
                op[hidx(m0,     n0    )] = acc[mt][nt][0] + bv0;
                op[hidx(m0,     n0 + 1)] = acc[mt][nt][1] + bv1;
                op[hidx(m0 + 8, n0    )] = acc[mt][nt][2] + bv0;
                op[hidx(m0 + 8, n0 + 1)] = acc[mt][nt][3] + bv1;
            } else {
                op[(size_t)m0*Dd + n0]         = acc[mt][nt][0] + bv0;
                op[(size_t)m0*Dd + n0 + 1]     = acc[mt][nt][1] + bv1;
                op[(size_t)(m0+8)*Dd + n0]     = acc[mt][nt][2] + bv0;
                op[(size_t)(m0+8)*Dd + n0 + 1] = acc[mt][nt][3] + bv1;
            }
        }
    }
}

// ---------------------------------------------------------------------------
// Attention: per (b,h) head, per 64-row q tile.
// Pass 1: stream K tiles, flash-stats (rowmax, rowsumexp) in registers.
// Pass 2: recompute scores, write normalized attention (final output) and
//         accumulate A@V via second mma from smem-staged P.
// 8 warps, grid 4(m) x 2(n), warp tile 16(q) x 32(k / dk).
// ---------------------------------------------------------------------------
#define AST 68   // smem row stride (floats)

__global__ void __launch_bounds__(256)
attn_kernel(const int* __restrict__ mask, float* __restrict__ att)
{
    extern __shared__ float sm_f[];
    float* Qs = sm_f;                 // 64*AST
    float* Ks = Qs + 64*AST;          // 64*AST
    float* Vs = Ks + 64*AST;          // 64*AST (stored transposed: Vs[dk][kc])
    float* Ps = Vs + 64*AST;          // 64*AST
    float* stat_m = Ps + 64*AST;      // 2*64
    float* stat_l = stat_m + 128;     // 2*64
    float* fin_m  = stat_l + 128;     // 64
    float* fin_il = fin_m + 64;       // 64
    int*   maskv  = (int*)(fin_il + 64); // 64

    const int tid = threadIdx.x;
    const int lane = tid & 31, w = tid >> 5;
    const int wm = w >> 1, wn = w & 1;
    const int g = lane >> 2, tg = lane & 3;
    const int qb = blockIdx.x, bh = blockIdx.y;
    const int b = bh >> 4;
    const int h = bh & 15;

    const float* Qb = g_Qh + ((size_t)bh*Ss + qb*64) * DKk;
    const float* Kb = g_Kh + (size_t)bh*Ss*DKk;
    const float* Vb = g_Vh + (size_t)bh*Ss*DKk;

    // Load Q tile once (scaled by 1/sqrt(Dk) = 0.125)
    {
        int r = tid >> 4, c = (tid & 15) * 4;
        #pragma unroll
        for (int i = 0; i < 4; i++) {
            int rr = r + i*16;
            float4 v = *(const float4*)(Qb + rr*64 + c);
            float4 o;
            o.x = f2tff(v.x * 0.125f); o.y = f2tff(v.y * 0.125f);
            o.z = f2tff(v.z * 0.125f); o.w = f2tff(v.w * 0.125f);
            *(float4*)&Qs[rr*AST + c] = o;
        }
    }

    const int qrow = wm*16 + g;
    float m_run[2] = {-1e30f, -1e30f};
    float l_run[2] = {0.f, 0.f};

    // ----------------- Pass 1: stats -----------------
    for (int kt = 0; kt < Ss/64; kt++) {
        __syncthreads();
        {
            int r = tid >> 4, c = (tid & 15) * 4;
            #pragma unroll
            for (int i = 0; i < 4; i++) {
                int rr = r + i*16;
                float4 v = *(const float4*)(Kb + (size_t)(kt*64 + rr)*64 + c);
                float4 o;
                o.x = f2tff(v.x); o.y = f2tff(v.y); o.z = f2tff(v.z); o.w = f2tff(v.w);
                *(float4*)&Ks[rr*AST + c] = o;
            }
            if (tid < 64) maskv[tid] = mask[b*Ss + kt*64 + tid];
        }
        __syncthreads();

        float sa[4][4];
        #pragma unroll
        for (int nt = 0; nt < 4; nt++)
            #pragma unroll
            for (int j = 0; j < 4; j++) sa[nt][j] = 0.f;

        #pragma unroll
        for (int k8 = 0; k8 < 64; k8 += 8) {
            unsigned a0 = __float_as_uint(Qs[qrow*AST     + k8 + tg]);
            unsigned a1 = __float_as_uint(Qs[(qrow+8)*AST + k8 + tg]);
            unsigned a2 = __float_as_uint(Qs[qrow*AST     + k8 + tg + 4]);
            unsigned a3 = __float_as_uint(Qs[(qrow+8)*AST + k8 + tg + 4]);
            #pragma unroll
            for (int nt = 0; nt < 4; nt++) {
                int n = wn*32 + nt*8 + g;
                unsigned b0 = __float_as_uint(Ks[n*AST + k8 + tg]);
                unsigned b1 = __float_as_uint(Ks[n*AST + k8 + tg + 4]);
                mma8(sa[nt], a0, a1, a2, a3, b0, b1);
            }
        }
        #pragma unroll
        for (int nt = 0; nt < 4; nt++) {
            int c = wn*32 + nt*8 + tg*2;
            if (maskv[c]   == 0) { sa[nt][0] = -1e9f; sa[nt][2] = -1e9f; }
            if (maskv[c+1] == 0) { sa[nt][1] = -1e9f; sa[nt][3] = -1e9f; }
        }
        #pragma unroll
        for (int e = 0; e < 2; e++) {
            float mx = -1e30f;
            #pragma unroll
            for (int nt = 0; nt < 4; nt++)
                mx = fmaxf(mx, fmaxf(sa[nt][2*e], sa[nt][2*e+1]));
            mx = fmaxf(mx, __shfl_xor_sync(0xffffffffu, mx, 1));
            mx = fmaxf(mx, __shfl_xor_sync(0xffffffffu, mx, 2));
            float mn = fmaxf(m_run[e], mx);
            float s = 0.f;
            #pragma unroll
            for (int nt = 0; nt < 4; nt++)
                s += __expf(sa[nt][2*e] - mn) + __expf(sa[nt][2*e+1] - mn);
            s += __shfl_xor_sync(0xffffffffu, s, 1);
            s += __shfl_xor_sync(0xffffffffu, s, 2);
            l_run[e] = l_run[e] * __expf(m_run[e] - mn) + s;
            m_run[e] = mn;
        }
    }

    // merge the two warp_n halves
    if (tg == 0) {
        stat_m[wn*64 + qrow]     = m_run[0];  stat_l[wn*64 + qrow]     = l_run[0];
        stat_m[wn*64 + qrow + 8] = m_run[1];  stat_l[wn*64 + qrow + 8] = l_run[1];
    }
    __syncthreads();
    if (tid < 64) {
        float m0 = stat_m[tid], m1 = stat_m[64 + tid];
        float mm = fmaxf(m0, m1);
        float ll = stat_l[tid] * __expf(m0 - mm) + stat_l[64 + tid] * __expf(m1 - mm);
        fin_m[tid]  = mm;
        fin_il[tid] = 1.0f / ll;
    }
    __syncthreads();
    float fm[2], fil[2];
    fm[0] = fin_m[qrow];     fil[0] = fin_il[qrow];
    fm[1] = fin_m[qrow + 8]; fil[1] = fin_il[qrow + 8];

    // ----------------- Pass 2: write attention + A@V -----------------
    float av[4][4];
    #pragma unroll
    for (int nt = 0; nt < 4; nt++)
        #pragma unroll
        for (int j = 0; j < 4; j++) av[nt][j] = 0.f;

    for (int kt = 0; kt < Ss/64; kt++) {
        __syncthreads();
        {
            int r = tid >> 4, c = (tid & 15) * 4;
            #pragma unroll
            for (int i = 0; i < 4; i++) {
                int rr = r + i*16;
                float4 v = *(const float4*)(Kb + (size_t)(kt*64 + rr)*64 + c);
                float4 o;
                o.x = f2tff(v.x); o.y = f2tff(v.y); o.z = f2tff(v.z); o.w = f2tff(v.w);
                *(float4*)&Ks[rr*AST + c] = o;
                float4 vv = *(const float4*)(Vb + (size_t)(kt*64 + rr)*64 + c);
                Vs[(c+0)*AST + rr] = f2tff(vv.x);
                Vs[(c+1)*AST + rr] = f2tff(vv.y);
                Vs[(c+2)*AST + rr] = f2tff(vv.z);
                Vs[(c+3)*AST + rr] = f2tff(vv.w);
            }
            if (tid < 64) maskv[tid] = mask[b*Ss + kt*64 + tid];
        }
        __syncthreads();

        float sa[4][4];
        #pragma unroll
        for (int nt = 0; nt < 4; nt++)
            #pragma unroll
            for (int j = 0; j < 4; j++) sa[nt][j] = 0.f;

        #pragma unroll
        for (int k8 = 0; k8 < 64; k8 += 8) {
            unsigned a0 = __float_as_uint(Qs[qrow*AST     + k8 + tg]);
            unsigned a1 = __float_as_uint(Qs[(qrow+8)*AST + k8 + tg]);
            unsigned a2 = __float_as_uint(Qs[qrow*AST     + k8 + tg + 4]);
            unsigned a3 = __float_as_uint(Qs[(qrow+8)*AST + k8 + tg + 4]);
            #pragma unroll
            for (int nt = 0; nt < 4; nt++) {
                int n = wn*32 + nt*8 + g;
                unsigned b0 = __float_as_uint(Ks[n*AST + k8 + tg]);
                unsigned b1 = __float_as_uint(Ks[n*AST + k8 + tg + 4]);
                mma8(sa[nt], a0, a1, a2, a3, b0, b1);
            }
        }
        #pragma unroll
        for (int nt = 0; nt < 4; nt++) {
            int c = wn*32 + nt*8 + tg*2;
            if (maskv[c]   == 0) { sa[nt][0] = -1e9f; sa[nt][2] = -1e9f; }
            if (maskv[c+1] == 0) { sa[nt][1] = -1e9f; sa[nt][3] = -1e9f; }
        }

        #pragma unroll
        for (int nt = 0; nt < 4; nt++) {
            int c = wn*32 + nt*8 + tg*2;
            #pragma unroll
            for (int e = 0; e < 2; e++) {
                float p0 = __expf(sa[nt][2*e]   - fm[e]) * fil[e];
                float p1 = __expf(sa[nt][2*e+1] - fm[e]) * fil[e];
                int rloc = qrow + 8*e;
                if (att) {
                    size_t qg = (size_t)bh*Ss + (qb*64 + rloc);
                    *(float2*)&att[qg*Ss + kt*64 + c] = make_float2(p0, p1);
                }
                *(float2*)&Ps[rloc*AST + c] = make_float2(f2tff(p0), f2tff(p1));
            }
        }
        __syncthreads();

        #pragma unroll
        for (int k8 = 0; k8 < 64; k8 += 8) {
            unsigned a0 = __float_as_uint(Ps[qrow*AST     + k8 + tg]);
            unsigned a1 = __float_as_uint(Ps[(qrow+8)*AST + k8 + tg]);
            unsigned a2 = __float_as_uint(Ps[qrow*AST     + k8 + tg + 4]);
            unsigned a3 = __float_as_uint(Ps[(qrow+8)*AST + k8 + tg + 4]);
            #pragma unroll
            for (int nt = 0; nt < 4; nt++) {
                int n = wn*32 + nt*8 + g;
                unsigned b0 = __float_as_uint(Vs[n*AST + k8 + tg]);
                unsigned b1 = __float_as_uint(Vs[n*AST + k8 + tg + 4]);
                mma8(av[nt], a0, a1, a2, a3, b0, b1);
            }
        }
    }

    // ctx epilogue: ctx[b][s][h*64+dk]
    #pragma unroll
    for (int nt = 0; nt < 4; nt++) {
        int dk = wn*32 + nt*8 + tg*2;
        #pragma unroll
        for (int e = 0; e < 2; e++) {
            int srow = qb*64 + qrow + 8*e;
            size_t idx = ((size_t)b*Ss + srow)*Dd + h*DKk + dk;
            g_ctx[idx]     = av[nt][2*e];
            g_ctx[idx + 1] = av[nt][2*e+1];
        }
    }
}

// ---------------------------------------------------------------------------

extern "C" void kernel_launch(void* const* d_in, const int* in_sizes, int n_in,
                              void* d_out, int out_size)
{
    const float* q    = (const float*)d_in[0];
    const float* k    = (const float*)d_in[1];
    const float* v    = (const float*)d_in[2];
    const int*   mask = (const int*)  d_in[3];
    const float* wq_w = (const float*)d_in[4];
    const float* wq_b = (const float*)d_in[5];
    const float* wk_w = (const float*)d_in[6];
    const float* wk_b = (const float*)d_in[7];
    const float* wv_w = (const float*)d_in[8];
    const float* wv_b = (const float*)d_in[9];
    const float* wo_w = (const float*)d_in[10];
    const float* wo_b = (const float*)d_in[11];

    float* out = (float*)d_out;
    float* att = nullptr;
    long long need = (long long)Bb*Ss*Dd + (long long)Bb*Hh*Ss*Ss;
    if ((long long)out_size >= need) att = out + (size_t)Bb*Ss*Dd;

    const int attn_smem = (4*64*AST + 128 + 128 + 64 + 64) * 4 + 64 * 4;
    cudaFuncSetAttribute(attn_kernel, cudaFuncAttributeMaxDynamicSharedMemorySize,
                         attn_smem);

    dim3 gp(Dd/128, Mm/128);  // (8, 32)
    gemm_proj<<<gp, 256>>>(q, wq_w, wq_b, nullptr, 0);
    gemm_proj<<<gp, 256>>>(k, wk_w, wk_b, nullptr, 1);
    gemm_proj<<<gp, 256>>>(v, wv_w, wv_b, nullptr, 2);

    attn_kernel<<<dim3(Ss/64, Bb*Hh), 256, attn_smem>>>(mask, att);

    gemm_proj<<<gp, 256>>>(nullptr, wo_w, wo_b, out, 3);
}

// round 5
// speedup vs baseline: 1.3920x; 1.3920x over previous
#include <cuda_runtime.h>
#include <cstdint>

#define Bb 2
#define Ss 2048
#define Dd 1024
#define Hh 16
#define DKk 64
#define Mm (Bb*Ss)
#define NTILE (Ss/64)

// Scratch (allocation-free rule: __device__ globals). Values stored tf32-rounded.
__device__ float g_Qh[(size_t)Bb*Hh*Ss*DKk];   // holds Qh * 0.125 (tf32-exact scale)
__device__ float g_Kh[(size_t)Bb*Hh*Ss*DKk];
__device__ float g_Vh[(size_t)Bb*Hh*Ss*DKk];
__device__ float g_ctx[(size_t)Bb*Ss*Dd];

__device__ __forceinline__ unsigned f2tf(float x){
    unsigned u; asm("cvt.rna.tf32.f32 %0, %1;" : "=r"(u) : "f"(x)); return u;
}
__device__ __forceinline__ float f2tff(float x){ return __uint_as_float(f2tf(x)); }

__device__ __forceinline__ void mma8(float* c,
    unsigned a0, unsigned a1, unsigned a2, unsigned a3,
    unsigned b0, unsigned b1)
{
    asm volatile(
      "mma.sync.aligned.m16n8k8.row.col.f32.tf32.tf32.f32 "
      "{%0,%1,%2,%3},{%4,%5,%6,%7},{%8,%9},{%0,%1,%2,%3};\n"
      : "+f"(c[0]), "+f"(c[1]), "+f"(c[2]), "+f"(c[3])
      : "r"(a0), "r"(a1), "r"(a2), "r"(a3), "r"(b0), "r"(b1));
}

__device__ __forceinline__ uint32_t sptr(const void* p){
    return (uint32_t)__cvta_generic_to_shared(p);
}
__device__ __forceinline__ void cpa16(uint32_t s, const void* g){
    asm volatile("cp.async.ca.shared.global [%0], [%1], 16;\n" :: "r"(s), "l"(g));
}
__device__ __forceinline__ void cpa4(uint32_t s, const void* g){
    asm volatile("cp.async.ca.shared.global [%0], [%1], 4;\n" :: "r"(s), "l"(g));
}
__device__ __forceinline__ void cp_commit(){ asm volatile("cp.async.commit_group;\n"); }
template<int N> __device__ __forceinline__ void cp_wait(){
    asm volatile("cp.async.wait_group %0;\n" :: "n"(N));
}

// head-layout index: m=(b*S+s), n=(h*64+dk) -> [b][h][s][dk]
__device__ __forceinline__ size_t hidx(int m, int n){
    int b = m >> 11;
    int s = m & 2047;
    int h = n >> 6;
    int dk = n & 63;
    return (((size_t)b*Hh + h)*Ss + s)*DKk + dk;
}

// ---------------------------------------------------------------------------
// Projection GEMM: C[4096,1024] = X @ W^T + bias.
// Block 128x128, BK=32, 8 warps (2m x 4n). Prefetch next k-tile LDGs before
// mma of current tile (hide DRAM latency behind tensor work).
// ---------------------------------------------------------------------------
#define PST 36

template<bool HEADOUT>
__device__ __forceinline__ void gemm_body(const float* __restrict__ Xp,
                                          const float* __restrict__ W,
                                          const float* __restrict__ bias,
                                          float* __restrict__ op,
                                          float oscale)
{
    __shared__ float As[128*PST];
    __shared__ float Bs[128*PST];

    const int tid = threadIdx.x;
    const int lane = tid & 31, w = tid >> 5;
    const int wm = w >> 2, wn = w & 3;
    const int g = lane >> 2, tg = lane & 3;
    const int by = blockIdx.y, bx = blockIdx.x;
    const int lr = tid >> 3, lc = (tid & 7) * 4;

    float acc[4][4][4];
    #pragma unroll
    for (int mt = 0; mt < 4; mt++)
        #pragma unroll
        for (int nt = 0; nt < 4; nt++)
            #pragma unroll
            for (int j = 0; j < 4; j++) acc[mt][nt][j] = 0.f;

    const float* xblk = Xp + (size_t)(by*128) * Dd;
    const float* wblk = W  + (size_t)(bx*128) * Dd;

    float4 xa[4], wa[4];
    #pragma unroll
    for (int i = 0; i < 4; i++) {
        xa[i] = *(const float4*)(xblk + (size_t)(lr + 32*i)*Dd + lc);
        wa[i] = *(const float4*)(wblk + (size_t)(lr + 32*i)*Dd + lc);
    }

    for (int kt = 0; kt < Dd/32; kt++) {
        __syncthreads();
        #pragma unroll
        for (int i = 0; i < 4; i++) {
            int r = lr + 32*i;
            As[r*PST + lc + 0] = f2tff(xa[i].x);
            As[r*PST + lc + 1] = f2tff(xa[i].y);
            As[r*PST + lc + 2] = f2tff(xa[i].z);
            As[r*PST + lc + 3] = f2tff(xa[i].w);
            Bs[r*PST + lc + 0] = f2tff(wa[i].x);
            Bs[r*PST + lc + 1] = f2tff(wa[i].y);
            Bs[r*PST + lc + 2] = f2tff(wa[i].z);
            Bs[r*PST + lc + 3] = f2tff(wa[i].w);
        }
        __syncthreads();

        if (kt + 1 < Dd/32) {
            #pragma unroll
            for (int i = 0; i < 4; i++) {
                xa[i] = *(const float4*)(xblk + (size_t)(lr + 32*i)*Dd + (kt+1)*32 + lc);
                wa[i] = *(const float4*)(wblk + (size_t)(lr + 32*i)*Dd + (kt+1)*32 + lc);
            }
        }

        #pragma unroll
        for (int k8 = 0; k8 < 32; k8 += 8) {
            unsigned a[4][4], bfr[4][2];
            #pragma unroll
            for (int mt = 0; mt < 4; mt++) {
                int r = wm*64 + mt*16 + g;
                a[mt][0] = __float_as_uint(As[r*PST     + k8 + tg]);
                a[mt][1] = __float_as_uint(As[(r+8)*PST + k8 + tg]);
                a[mt][2] = __float_as_uint(As[r*PST     + k8 + tg + 4]);
                a[mt][3] = __float_as_uint(As[(r+8)*PST + k8 + tg + 4]);
            }
            #pragma unroll
            for (int nt = 0; nt < 4; nt++) {
                int n = wn*32 + nt*8 + g;
                bfr[nt][0] = __float_as_uint(Bs[n*PST + k8 + tg]);
                bfr[nt][1] = __float_as_uint(Bs[n*PST + k8 + tg + 4]);
            }
            #pragma unroll
            for (int mt = 0; mt < 4; mt++)
                #pragma unroll
                for (int nt = 0; nt < 4; nt++)
                    mma8(acc[mt][nt], a[mt][0], a[mt][1], a[mt][2], a[mt][3],
                         bfr[nt][0], bfr[nt][1]);
        }
    }

    #pragma unroll
    for (int mt = 0; mt < 4; mt++) {
        int m0 = by*128 + wm*64 + mt*16 + g;
        #pragma unroll
        for (int nt = 0; nt < 4; nt++) {
            int n0 = bx*128 + wn*32 + nt*8 + tg*2;
            float bv0 = bias[n0], bv1 = bias[n0 + 1];
            if (HEADOUT) {
                op[hidx(m0,     n0    )] = f2tff((acc[mt][nt][0] + bv0) * oscale);
                op[hidx(m0,     n0 + 1)] = f2tff((acc[mt][nt][1] + bv1) * oscale);
                op[hidx(m0 + 8, n0    )] = f2tff((acc[mt][nt][2] + bv0) * oscale);
                op[hidx(m0 + 8, n0 + 1)] = f2tff((acc[mt][nt][3] + bv1) * oscale);
            } else {
                op[(size_t)m0*Dd + n0]         = acc[mt][nt][0] + bv0;
                op[(size_t)m0*Dd + n0 + 1]     = acc[mt][nt][1] + bv1;
                op[(size_t)(m0+8)*Dd + n0]     = acc[mt][nt][2] + bv0;
                op[(size_t)(m0+8)*Dd + n0 + 1] = acc[mt][nt][3] + bv1;
            }
        }
    }
}

__global__ void __launch_bounds__(256)
gemm_qkv(const float* __restrict__ q, const float* __restrict__ k,
         const float* __restrict__ v,
         const float* __restrict__ wq, const float* __restrict__ wk,
         const float* __restrict__ wv,
         const float* __restrict__ bq, const float* __restrict__ bk,
         const float* __restrict__ bv)
{
    int mode = blockIdx.z;
    const float* X = (mode == 0) ? q : (mode == 1) ? k : v;
    const float* W = (mode == 0) ? wq : (mode == 1) ? wk : wv;
    const float* B = (mode == 0) ? bq : (mode == 1) ? bk : bv;
    float* op = (mode == 0) ? g_Qh : (mode == 1) ? g_Kh : g_Vh;
    float sc = (mode == 0) ? 0.125f : 1.0f;   // fold 1/sqrt(Dk) into Q (tf32-exact)
    gemm_body<true>(X, W, B, op, sc);
}

__global__ void __launch_bounds__(256)
gemm_o(const float* __restrict__ W, const float* __restrict__ bias,
       float* __restrict__ outp)
{
    gemm_body<false>(g_ctx, W, bias, outp, 1.0f);
}

// ---------------------------------------------------------------------------
// Attention. q-tile = 128 rows/block, 8 warps = 4 wm x 2 wn, warp tile 32x32.
// Pass 1: cp.async double-buffered K stream, sumexp only (no running max).
// Pass 2: recompute scores, write normalized attention, P->smem, AV mma with
//         B-frags read directly from row-major Vs.
// ---------------------------------------------------------------------------
#define AST 68
#define BQ 128

__global__ void __launch_bounds__(256)
attn_kernel(const int* __restrict__ mask, float* __restrict__ att)
{
    extern __shared__ float sm[];
    float* Qs  = sm;                    // 128*68
    float* Kb0 = Qs  + BQ*AST;          // 64*68
    float* Kb1 = Kb0 + 64*AST;
    float* Vb0 = Kb1 + 64*AST;
    float* Vb1 = Vb0 + 64*AST;
    float* Ps  = Vb1 + 64*AST;          // 128*68
    float* stat_l = Ps + BQ*AST;        // 256
    float* fin_il = stat_l + 256;       // 128
    int*   maskv  = (int*)(fin_il + 128); // 2*64

    const int tid = threadIdx.x;
    const int lane = tid & 31, w = tid >> 5;
    const int wm = w >> 1, wn = w & 1;
    const int g = lane >> 2, tg = lane & 3;
    const int qb = blockIdx.x, bh = blockIdx.y;
    const int b = bh >> 4, h = bh & 15;

    const float* Qg = g_Qh + ((size_t)bh*Ss + qb*BQ) * DKk;
    const float* Kg = g_Kh + (size_t)bh*Ss*DKk;
    const float* Vg = g_Vh + (size_t)bh*Ss*DKk;
    const int*   mg = mask + b*Ss;

    const int lr = tid >> 4, lc = (tid & 15) * 4;

    // prologue: Q tile + K tile 0 + mask 0 (group 0)
    #pragma unroll
    for (int i = 0; i < 8; i++)
        cpa16(sptr(&Qs[(lr + 16*i)*AST + lc]), Qg + (lr + 16*i)*64 + lc);
    #pragma unroll
    for (int i = 0; i < 4; i++)
        cpa16(sptr(&Kb0[(lr + 16*i)*AST + lc]), Kg + (lr + 16*i)*64 + lc);
    if (tid < 64) cpa4(sptr(&maskv[tid]), mg + tid);
    cp_commit();

    // ----------------- Pass 1: row sumexp -----------------
    float lpart[2][2] = {{0.f,0.f},{0.f,0.f}};

    for (int kt = 0; kt < NTILE; kt++) {
        int cur = kt & 1;
        float* Ksb = cur ? Kb1 : Kb0;
        const int* mk = maskv + cur*64;

        if (kt + 1 < NTILE) {
            float* Kn = cur ? Kb0 : Kb1;
            const float* src = Kg + (size_t)(kt+1)*64*64;
            #pragma unroll
            for (int i = 0; i < 4; i++)
                cpa16(sptr(&Kn[(lr + 16*i)*AST + lc]), src + (lr + 16*i)*64 + lc);
            if (tid < 64) cpa4(sptr(&maskv[(1-cur)*64 + tid]), mg + (kt+1)*64 + tid);
            cp_commit();
            cp_wait<1>();
        } else {
            cp_wait<0>();
        }
        __syncthreads();

        float sa[2][4][4];
        #pragma unroll
        for (int mt = 0; mt < 2; mt++)
            #pragma unroll
            for (int nt = 0; nt < 4; nt++)
                #pragma unroll
                for (int j = 0; j < 4; j++) sa[mt][nt][j] = 0.f;

        #pragma unroll
        for (int k8 = 0; k8 < 64; k8 += 8) {
            unsigned a[2][4];
            #pragma unroll
            for (int mt = 0; mt < 2; mt++) {
                int qr = wm*32 + mt*16 + g;
                a[mt][0] = __float_as_uint(Qs[qr*AST     + k8 + tg]);
                a[mt][1] = __float_as_uint(Qs[(qr+8)*AST + k8 + tg]);
                a[mt][2] = __float_as_uint(Qs[qr*AST     + k8 + tg + 4]);
                a[mt][3] = __float_as_uint(Qs[(qr+8)*AST + k8 + tg + 4]);
            }
            #pragma unroll
            for (int nt = 0; nt < 4; nt++) {
                int n = wn*32 + nt*8 + g;
                unsigned b0 = __float_as_uint(Ksb[n*AST + k8 + tg]);
                unsigned b1 = __float_as_uint(Ksb[n*AST + k8 + tg + 4]);
                #pragma unroll
                for (int mt = 0; mt < 2; mt++)
                    mma8(sa[mt][nt], a[mt][0], a[mt][1], a[mt][2], a[mt][3], b0, b1);
            }
        }

        #pragma unroll
        for (int nt = 0; nt < 4; nt++) {
            int c0 = wn*32 + nt*8 + 2*tg;
            int m0 = mk[c0], m1 = mk[c0 + 1];
            #pragma unroll
            for (int mt = 0; mt < 2; mt++) {
                float s0 = m0 ? sa[mt][nt][0] : -1e9f;
                float s1 = m1 ? sa[mt][nt][1] : -1e9f;
                float s2 = m0 ? sa[mt][nt][2] : -1e9f;
                float s3 = m1 ? sa[mt][nt][3] : -1e9f;
                lpart[mt][0] += __expf(s0) + __expf(s1);
                lpart[mt][1] += __expf(s2) + __expf(s3);
            }
        }
        __syncthreads();
    }

    // issue pass-2 tile 0 (K+V+mask) while merging stats
    {
        #pragma unroll
        for (int i = 0; i < 4; i++) {
            cpa16(sptr(&Kb0[(lr + 16*i)*AST + lc]), Kg + (lr + 16*i)*64 + lc);
            cpa16(sptr(&Vb0[(lr + 16*i)*AST + lc]), Vg + (lr + 16*i)*64 + lc);
        }
        if (tid < 64) cpa4(sptr(&maskv[tid]), mg + tid);
        cp_commit();
    }

    #pragma unroll
    for (int mt = 0; mt < 2; mt++)
        #pragma unroll
        for (int e = 0; e < 2; e++) {
            float l = lpart[mt][e];
            l += __shfl_xor_sync(0xffffffffu, l, 1);
            l += __shfl_xor_sync(0xffffffffu, l, 2);
            if (tg == 0) stat_l[wn*128 + wm*32 + mt*16 + g + 8*e] = l;
        }
    __syncthreads();
    if (tid < 128) fin_il[tid] = 1.0f / (stat_l[tid] + stat_l[128 + tid]);
    __syncthreads();

    float fil[2][2];
    #pragma unroll
    for (int mt = 0; mt < 2; mt++)
        #pragma unroll
        for (int e = 0; e < 2; e++)
            fil[mt][e] = fin_il[wm*32 + mt*16 + g + 8*e];

    // ----------------- Pass 2: attention write + A@V -----------------
    float av[2][4][4];
    #pragma unroll
    for (int mt = 0; mt < 2; mt++)
        #pragma unroll
        for (int nt = 0; nt < 4; nt++)
            #pragma unroll
            for (int j = 0; j < 4; j++) av[mt][nt][j] = 0.f;

    for (int kt = 0; kt < NTILE; kt++) {
        int cur = kt & 1;
        float* Ksb = cur ? Kb1 : Kb0;
        float* Vsb = cur ? Vb1 : Vb0;
        const int* mk = maskv + cur*64;

        if (kt + 1 < NTILE) {
            float* Kn = cur ? Kb0 : Kb1;
            float* Vn = cur ? Vb0 : Vb1;
            const float* ksrc = Kg + (size_t)(kt+1)*64*64;
            const float* vsrc = Vg + (size_t)(kt+1)*64*64;
            #pragma unroll
            for (int i = 0; i < 4; i++) {
                cpa16(sptr(&Kn[(lr + 16*i)*AST + lc]), ksrc + (lr + 16*i)*64 + lc);
                cpa16(sptr(&Vn[(lr + 16*i)*AST + lc]), vsrc + (lr + 16*i)*64 + lc);
            }
            if (tid < 64) cpa4(sptr(&maskv[(1-cur)*64 + tid]), mg + (kt+1)*64 + tid);
            cp_commit();
            cp_wait<1>();
        } else {
            cp_wait<0>();
        }
        __syncthreads();

        float sa[2][4][4];
        #pragma unroll
        for (int mt = 0; mt < 2; mt++)
            #pragma unroll
            for (int nt = 0; nt < 4; nt++)
                #pragma unroll
                for (int j = 0; j < 4; j++) sa[mt][nt][j] = 0.f;

        #pragma unroll
        for (int k8 = 0; k8 < 64; k8 += 8) {
            unsigned a[2][4];
            #pragma unroll
            for (int mt = 0; mt < 2; mt++) {
                int qr = wm*32 + mt*16 + g;
                a[mt][0] = __float_as_uint(Qs[qr*AST     + k8 + tg]);
                a[mt][1] = __float_as_uint(Qs[(qr+8)*AST + k8 + tg]);
                a[mt][2] = __float_as_uint(Qs[qr*AST     + k8 + tg + 4]);
                a[mt][3] = __float_as_uint(Qs[(qr+8)*AST + k8 + tg + 4]);
            }
            #pragma unroll
            for (int nt = 0; nt < 4; nt++) {
                int n = wn*32 + nt*8 + g;
                unsigned b0 = __float_as_uint(Ksb[n*AST + k8 + tg]);
                unsigned b1 = __float_as_uint(Ksb[n*AST + k8 + tg + 4]);
                #pragma unroll
                for (int mt = 0; mt < 2; mt++)
                    mma8(sa[mt][nt], a[mt][0], a[mt][1], a[mt][2], a[mt][3], b0, b1);
            }
        }

        #pragma unroll
        for (int nt = 0; nt < 4; nt++) {
            int c0 = wn*32 + nt*8 + 2*tg;
            int m0 = mk[c0], m1 = mk[c0 + 1];
            #pragma unroll
            for (int mt = 0; mt < 2; mt++) {
                #pragma unroll
                for (int e = 0; e < 2; e++) {
                    float p0 = m0 ? __expf(sa[mt][nt][2*e])   * fil[mt][e] : 0.f;
                    float p1 = m1 ? __expf(sa[mt][nt][2*e+1]) * fil[mt][e] : 0.f;
                    int qr = wm*32 + mt*16 + g + 8*e;
                    if (att) {
                        size_t qglob = (size_t)bh*Ss + qb*BQ + qr;
                        *(float2*)&att[qglob*Ss + kt*64 + c0] = make_float2(p0, p1);
                    }
                    *(float2*)&Ps[qr*AST + c0] = make_float2(f2tff(p0), f2tff(p1));
                }
            }
        }
        __syncthreads();

        #pragma unroll
        for (int k8 = 0; k8 < 64; k8 += 8) {
            unsigned a[2][4];
            #pragma unroll
            for (int mt = 0; mt < 2; mt++) {
                int qr = wm*32 + mt*16 + g;
                a[mt][0] = __float_as_uint(Ps[qr*AST     + k8 + tg]);
                a[mt][1] = __float_as_uint(Ps[(qr+8)*AST + k8 + tg]);
                a[mt][2] = __float_as_uint(Ps[qr*AST     + k8 + tg + 4]);
                a[mt][3] = __float_as_uint(Ps[(qr+8)*AST + k8 + tg + 4]);
            }
            #pragma unroll
            for (int nt = 0; nt < 4; nt++) {
                int n = wn*32 + nt*8 + g;
                unsigned b0 = __float_as_uint(Vsb[(k8+tg)*AST   + n]);
                unsigned b1 = __float_as_uint(Vsb[(k8+tg+4)*AST + n]);
                #pragma unroll
                for (int mt = 0; mt < 2; mt++)
                    mma8(av[mt][nt], a[mt][0], a[mt][1], a[mt][2], a[mt][3], b0, b1);
            }
        }
        __syncthreads();
    }

    // ctx epilogue: ctx[b][s][h*64+dk]
    #pragma unroll
    for (int mt = 0; mt < 2; mt++) {
        #pragma unroll
        for (int nt = 0; nt < 4; nt++) {
            int dk = wn*32 + nt*8 + 2*tg;
            #pragma unroll
            for (int e = 0; e < 2; e++) {
                int srow = qb*BQ + wm*32 + mt*16 + g + 8*e;
                size_t idx = ((size_t)b*Ss + srow)*Dd + h*DKk + dk;
                *(float2*)&g_ctx[idx] = make_float2(av[mt][nt][2*e], av[mt][nt][2*e+1]);
            }
        }
    }
}

// ---------------------------------------------------------------------------

extern "C" void kernel_launch(void* const* d_in, const int* in_sizes, int n_in,
                              void* d_out, int out_size)
{
    const float* q    = (const float*)d_in[0];
    const float* k    = (const float*)d_in[1];
    const float* v    = (const float*)d_in[2];
    const int*   mask = (const int*)  d_in[3];
    const float* wq_w = (const float*)d_in[4];
    const float* wq_b = (const float*)d_in[5];
    const float* wk_w = (const float*)d_in[6];
    const float* wk_b = (const float*)d_in[7];
    const float* wv_w = (const float*)d_in[8];
    const float* wv_b = (const float*)d_in[9];
    const float* wo_w = (const float*)d_in[10];
    const float* wo_b = (const float*)d_in[11];

    float* out = (float*)d_out;
    float* att = nullptr;
    long long need = (long long)Bb*Ss*Dd + (long long)Bb*Hh*Ss*Ss;
    if ((long long)out_size >= need) att = out + (size_t)Bb*Ss*Dd;

    const int attn_smem = ((BQ*AST)*2 + 4*64*AST + 256 + 128) * 4 + 2*64*4;
    static int configured = 0;
    cudaFuncSetAttribute(attn_kernel, cudaFuncAttributeMaxDynamicSharedMemorySize,
                         attn_smem);
    (void)configured;

    dim3 gqkv(Dd/128, Mm/128, 3);   // (8, 32, 3)
    gemm_qkv<<<gqkv, 256>>>(q, k, v, wq_w, wk_w, wv_w, wq_b, wk_b, wv_b);

    attn_kernel<<<dim3(Ss/BQ, Bb*Hh), 256, attn_smem>>>(mask, att);

    gemm_o<<<dim3(Dd/128, Mm/128), 256>>>(wo_w, wo_b, out);
}

// round 7
// speedup vs baseline: 2.1602x; 1.5518x over previous
#include <cuda_runtime.h>
#include <cuda_fp16.h>
#include <cstdint>

#define Bb 2
#define Ss 2048
#define Dd 1024
#define Hh 16
#define DKk 64
#define Mm (Bb*Ss)
#define NTILE (Ss/64)

// Scratch (allocation-free rule: __device__ globals). fp16 internal datapath.
__device__ __half g_Qh[(size_t)Bb*Hh*Ss*DKk];   // holds Qh * 0.125
__device__ __half g_Kh[(size_t)Bb*Hh*Ss*DKk];
__device__ __half g_Vh[(size_t)Bb*Hh*Ss*DKk];
__device__ __half g_ctx[(size_t)Bb*Ss*Dd];

// ---------------- PTX helpers ----------------
__device__ __forceinline__ uint32_t sptr(const void* p){
    return (uint32_t)__cvta_generic_to_shared(p);
}
__device__ __forceinline__ void cpa16(uint32_t s, const void* g){
    asm volatile("cp.async.ca.shared.global [%0], [%1], 16;\n" :: "r"(s), "l"(g));
}
__device__ __forceinline__ void cpa4(uint32_t s, const void* g){
    asm volatile("cp.async.ca.shared.global [%0], [%1], 4;\n" :: "r"(s), "l"(g));
}
__device__ __forceinline__ void cp_commit(){ asm volatile("cp.async.commit_group;\n"); }
template<int N> __device__ __forceinline__ void cp_wait(){
    asm volatile("cp.async.wait_group %0;\n" :: "n"(N));
}

__device__ __forceinline__ void ldsm4(uint32_t a, uint32_t* r){
    asm volatile("ldmatrix.sync.aligned.m8n8.x4.shared.b16 {%0,%1,%2,%3},[%4];\n"
        : "=r"(r[0]), "=r"(r[1]), "=r"(r[2]), "=r"(r[3]) : "r"(a));
}
__device__ __forceinline__ void ldsm4t(uint32_t a, uint32_t* r){
    asm volatile("ldmatrix.sync.aligned.m8n8.x4.trans.shared.b16 {%0,%1,%2,%3},[%4];\n"
        : "=r"(r[0]), "=r"(r[1]), "=r"(r[2]), "=r"(r[3]) : "r"(a));
}

__device__ __forceinline__ void mma16(float* c,
    uint32_t a0, uint32_t a1, uint32_t a2, uint32_t a3, uint32_t b0, uint32_t b1)
{
    asm volatile(
      "mma.sync.aligned.m16n8k16.row.col.f32.f16.f16.f32 "
      "{%0,%1,%2,%3},{%4,%5,%6,%7},{%8,%9},{%0,%1,%2,%3};\n"
      : "+f"(c[0]), "+f"(c[1]), "+f"(c[2]), "+f"(c[3])
      : "r"(a0), "r"(a1), "r"(a2), "r"(a3), "r"(b0), "r"(b1));
}

__device__ __forceinline__ void sth2(__half* p, float lo, float hi){
    *(__half2*)p = __floats2half2_rn(lo, hi);
}

// head-layout index: m=(b*S+s), n=(h*64+dk) -> [b][h][s][dk]
__device__ __forceinline__ size_t hidx(int m, int n){
    int b = m >> 11;
    int s = m & 2047;
    int h = n >> 6;
    int dk = n & 63;
    return (((size_t)b*Hh + h)*Ss + s)*DKk + dk;
}

// ---------------------------------------------------------------------------
// Projection GEMM: C[4096,1024] = X @ W^T + bias, fp16 mma m16n8k16.
// Block 128x128, BK=32, 8 warps (2m x 4n), warp 64x32. Register prefetch.
// ---------------------------------------------------------------------------
#define GST 40   // smem row stride in halves (80B rows, 16B-aligned, LDSM conflict-free)

template<bool XHALF, bool HEADOUT>
__device__ __forceinline__ void gemm_body(const void* __restrict__ Xpv,
                                          const float* __restrict__ W,
                                          const float* __restrict__ bias,
                                          void* __restrict__ opv,
                                          float oscale)
{
    __shared__ __half As[128*GST];
    __shared__ __half Bs[128*GST];

    const int tid = threadIdx.x;
    const int lane = tid & 31, w = tid >> 5;
    const int wm = w >> 2, wn = w & 3;
    const int g = lane >> 2, tg = lane & 3;
    const int by = blockIdx.y, bx = blockIdx.x;

    const int a_off_r = (lane & 7) + ((lane >> 3) & 1) * 8;
    const int a_off_c = (lane >> 4) << 3;
    const int b_off_r = (lane & 7) + ((lane >> 4) << 3);
    const int b_off_c = ((lane >> 3) & 1) << 3;

    const int lr = tid >> 3, lc = (tid & 7) * 4;   // fp32 loader
    const int hr = tid >> 2, hc = (tid & 3) * 8;   // half loader

    float acc[4][4][4];
    #pragma unroll
    for (int mt = 0; mt < 4; mt++)
        #pragma unroll
        for (int nt = 0; nt < 4; nt++)
            #pragma unroll
            for (int j = 0; j < 4; j++) acc[mt][nt][j] = 0.f;

    const float* wblk = W + (size_t)(bx*128) * Dd;
    const float* xblkf = XHALF ? nullptr : (const float*)Xpv + (size_t)(by*128) * Dd;
    const __half* xblkh = XHALF ? (const __half*)Xpv + (size_t)(by*128) * Dd : nullptr;

    float4 wa[4]; float4 xa[4]; uint4 xh[2];
    #pragma unroll
    for (int i = 0; i < 4; i++)
        wa[i] = *(const float4*)(wblk + (size_t)(lr + 32*i)*Dd + lc);
    if (XHALF) {
        #pragma unroll
        for (int i = 0; i < 2; i++)
            xh[i] = *(const uint4*)(xblkh + (size_t)(hr + 64*i)*Dd + hc);
    } else {
        #pragma unroll
        for (int i = 0; i < 4; i++)
            xa[i] = *(const float4*)(xblkf + (size_t)(lr + 32*i)*Dd + lc);
    }

    for (int kt = 0; kt < Dd/32; kt++) {
        __syncthreads();
        #pragma unroll
        for (int i = 0; i < 4; i++) {
            int r = lr + 32*i;
            sth2(&Bs[r*GST + lc],     wa[i].x, wa[i].y);
            sth2(&Bs[r*GST + lc + 2], wa[i].z, wa[i].w);
        }
        if (XHALF) {
            #pragma unroll
            for (int i = 0; i < 2; i++)
                *(uint4*)&As[(hr + 64*i)*GST + hc] = xh[i];
        } else {
            #pragma unroll
            for (int i = 0; i < 4; i++) {
                int r = lr + 32*i;
                sth2(&As[r*GST + lc],     xa[i].x, xa[i].y);
                sth2(&As[r*GST + lc + 2], xa[i].z, xa[i].w);
            }
        }
        __syncthreads();

        if (kt + 1 < Dd/32) {
            #pragma unroll
            for (int i = 0; i < 4; i++)
                wa[i] = *(const float4*)(wblk + (size_t)(lr + 32*i)*Dd + (kt+1)*32 + lc);
            if (XHALF) {
                #pragma unroll
                for (int i = 0; i < 2; i++)
                    xh[i] = *(const uint4*)(xblkh + (size_t)(hr + 64*i)*Dd + (kt+1)*32 + hc);
            } else {
                #pragma unroll
                for (int i = 0; i < 4; i++)
                    xa[i] = *(const float4*)(xblkf + (size_t)(lr + 32*i)*Dd + (kt+1)*32 + lc);
            }
        }

        #pragma unroll
        for (int ks = 0; ks < 32; ks += 16) {
            uint32_t aF[4][4], bF[2][4];
            #pragma unroll
            for (int mt = 0; mt < 4; mt++)
                ldsm4(sptr(&As[(wm*64 + mt*16 + a_off_r)*GST + ks + a_off_c]), aF[mt]);
            #pragma unroll
            for (int ntp = 0; ntp < 2; ntp++)
                ldsm4(sptr(&Bs[(wn*32 + ntp*16 + b_off_r)*GST + ks + b_off_c]), bF[ntp]);
            #pragma unroll
            for (int mt = 0; mt < 4; mt++)
                #pragma unroll
                for (int nt = 0; nt < 4; nt++)
                    mma16(acc[mt][nt], aF[mt][0], aF[mt][1], aF[mt][2], aF[mt][3],
                          bF[nt>>1][(nt&1)*2], bF[nt>>1][(nt&1)*2 + 1]);
        }
    }

    #pragma unroll
    for (int mt = 0; mt < 4; mt++) {
        int m0 = by*128 + wm*64 + mt*16 + g;
        #pragma unroll
        for (int nt = 0; nt < 4; nt++) {
            int n0 = bx*128 + wn*32 + nt*8 + tg*2;
            float bv0 = bias[n0], bv1 = bias[n0 + 1];
            if (HEADOUT) {
                __half* op = (__half*)opv;
                sth2(&op[hidx(m0,     n0)], (acc[mt][nt][0] + bv0) * oscale,
                                            (acc[mt][nt][1] + bv1) * oscale);
                sth2(&op[hidx(m0 + 8, n0)], (acc[mt][nt][2] + bv0) * oscale,
                                            (acc[mt][nt][3] + bv1) * oscale);
            } else {
                float* op = (float*)opv;
                *(float2*)&op[(size_t)m0*Dd + n0] =
                    make_float2(acc[mt][nt][0] + bv0, acc[mt][nt][1] + bv1);
                *(float2*)&op[(size_t)(m0+8)*Dd + n0] =
                    make_float2(acc[mt][nt][2] + bv0, acc[mt][nt][3] + bv1);
            }
        }
    }
}

__global__ void __launch_bounds__(256)
gemm_qkv(const float* __restrict__ q, const float* __restrict__ k,
         const float* __restrict__ v,
         const float* __restrict__ wq, const float* __restrict__ wk,
         const float* __restrict__ wv,
         const float* __restrict__ bq, const float* __restrict__ bk,
         const float* __restrict__ bv)
{
    int mode = blockIdx.z;
    const float* X = (mode == 0) ? q : (mode == 1) ? k : v;
    const float* W = (mode == 0) ? wq : (mode == 1) ? wk : wv;
    const float* B = (mode == 0) ? bq : (mode == 1) ? bk : bv;
    __half* op = (mode == 0) ? g_Qh : (mode == 1) ? g_Kh : g_Vh;
    float sc = (mode == 0) ? 0.125f : 1.0f;
    gemm_body<false, true>(X, W, B, op, sc);
}

__global__ void __launch_bounds__(256)
gemm_o(const float* __restrict__ W, const float* __restrict__ bias,
       float* __restrict__ outp)
{
    gemm_body<true, false>(g_ctx, W, bias, outp, 1.0f);
}

// ---------------------------------------------------------------------------
// Attention, fp16. q-tile = 128 rows, 8 warps = 4 wm x 2 wn, warp tile 32x32.
// Pass 1: cp.async double-buffered K stream, row sumexp (no running max).
// Pass 2: recompute scores, write normalized fp32 attention, P->smem half,
//         AV mma with LDSM A-frags (P) and LDSM.trans B-frags (row-major V).
// ---------------------------------------------------------------------------
#define HST 72   // smem row stride in halves (144B rows, 16B-aligned, conflict-free)
#define BQ 128

__global__ void __launch_bounds__(256)
attn_kernel(const int* __restrict__ mask, float* __restrict__ att)
{
    extern __shared__ __half smh[];
    __half* Qs  = smh;                  // 128*HST
    __half* Kb0 = Qs  + BQ*HST;         // 64*HST
    __half* Kb1 = Kb0 + 64*HST;
    __half* Vb0 = Kb1 + 64*HST;
    __half* Vb1 = Vb0 + 64*HST;
    __half* Ps  = Vb1 + 64*HST;         // 128*HST
    float* stat_l = (float*)(Ps + BQ*HST);  // 256
    float* fin_il = stat_l + 256;           // 128
    int*   maskv  = (int*)(fin_il + 128);   // 2*64

    const int tid = threadIdx.x;
    const int lane = tid & 31, w = tid >> 5;
    const int wm = w >> 1, wn = w & 1;
    const int g = lane >> 2, tg = lane & 3;
    const int qb = blockIdx.x, bh = blockIdx.y;
    const int b = bh >> 4, hd = bh & 15;

    const int a_off_r = (lane & 7) + ((lane >> 3) & 1) * 8;
    const int a_off_c = (lane >> 4) << 3;
    const int b_off_r = (lane & 7) + ((lane >> 4) << 3);
    const int b_off_c = ((lane >> 3) & 1) << 3;
    const int v_off_r = (lane & 7) + (((lane >> 3) & 1) << 3);
    const int v_off_c = (lane >> 4) << 3;

    const __half* Qg = g_Qh + ((size_t)bh*Ss + qb*BQ) * DKk;
    const __half* Kg = g_Kh + (size_t)bh*Ss*DKk;
    const __half* Vg = g_Vh + (size_t)bh*Ss*DKk;
    const int*    mg = mask + b*Ss;

    // prologue: Q tile (4 chunks/thread) + K tile 0 (2 chunks) + mask
    #pragma unroll
    for (int i = 0; i < 4; i++) {
        int id = tid + 256*i, r = id >> 3, c = (id & 7)*8;
        cpa16(sptr(&Qs[r*HST + c]), Qg + r*64 + c);
    }
    #pragma unroll
    for (int i = 0; i < 2; i++) {
        int id = tid + 256*i, r = id >> 3, c = (id & 7)*8;
        cpa16(sptr(&Kb0[r*HST + c]), Kg + r*64 + c);
    }
    if (tid < 64) cpa4(sptr(&maskv[tid]), mg + tid);
    cp_commit();

    // ----------------- Pass 1: row sumexp -----------------
    float lpart[2][2] = {{0.f,0.f},{0.f,0.f}};

    for (int kt = 0; kt < NTILE; kt++) {
        int cur = kt & 1;
        __half* Ksb = cur ? Kb1 : Kb0;
        const int* mk = maskv + cur*64;

        if (kt + 1 < NTILE) {
            __half* Kn = cur ? Kb0 : Kb1;
            const __half* src = Kg + (size_t)(kt+1)*64*64;
            #pragma unroll
            for (int i = 0; i < 2; i++) {
                int id = tid + 256*i, r = id >> 3, c = (id & 7)*8;
                cpa16(sptr(&Kn[r*HST + c]), src + r*64 + c);
            }
            if (tid < 64) cpa4(sptr(&maskv[(1-cur)*64 + tid]), mg + (kt+1)*64 + tid);
            cp_commit();
            cp_wait<1>();
        } else {
            cp_wait<0>();
        }
        __syncthreads();

        float sa[2][4][4];
        #pragma unroll
        for (int mt = 0; mt < 2; mt++)
            #pragma unroll
            for (int nt = 0; nt < 4; nt++)
                #pragma unroll
                for (int j = 0; j < 4; j++) sa[mt][nt][j] = 0.f;

        #pragma unroll
        for (int ks = 0; ks < 64; ks += 16) {
            uint32_t aF[2][4], bF[2][4];
            #pragma unroll
            for (int mt = 0; mt < 2; mt++)
                ldsm4(sptr(&Qs[(wm*32 + mt*16 + a_off_r)*HST + ks + a_off_c]), aF[mt]);
            #pragma unroll
            for (int ntp = 0; ntp < 2; ntp++)
                ldsm4(sptr(&Ksb[(wn*32 + ntp*16 + b_off_r)*HST + ks + b_off_c]), bF[ntp]);
            #pragma unroll
            for (int mt = 0; mt < 2; mt++)
                #pragma unroll
                for (int nt = 0; nt < 4; nt++)
                    mma16(sa[mt][nt], aF[mt][0], aF[mt][1], aF[mt][2], aF[mt][3],
                          bF[nt>>1][(nt&1)*2], bF[nt>>1][(nt&1)*2 + 1]);
        }

        #pragma unroll
        for (int nt = 0; nt < 4; nt++) {
            int c0 = wn*32 + nt*8 + 2*tg;
            int m0 = mk[c0], m1 = mk[c0 + 1];
            #pragma unroll
            for (int mt = 0; mt < 2; mt++) {
                float s0 = m0 ? sa[mt][nt][0] : -1e9f;
                float s1 = m1 ? sa[mt][nt][1] : -1e9f;
                float s2 = m0 ? sa[mt][nt][2] : -1e9f;
                float s3 = m1 ? sa[mt][nt][3] : -1e9f;
                lpart[mt][0] += __expf(s0) + __expf(s1);
                lpart[mt][1] += __expf(s2) + __expf(s3);
            }
        }
        __syncthreads();
    }

    // issue pass-2 tile 0 (K+V+mask) while merging stats
    #pragma unroll
    for (int i = 0; i < 2; i++) {
        int id = tid + 256*i, r = id >> 3, c = (id & 7)*8;
        cpa16(sptr(&Kb0[r*HST + c]), Kg + r*64 + c);
        cpa16(sptr(&Vb0[r*HST + c]), Vg + r*64 + c);
    }
    if (tid < 64) cpa4(sptr(&maskv[tid]), mg + tid);
    cp_commit();

    #pragma unroll
    for (int mt = 0; mt < 2; mt++)
        #pragma unroll
        for (int e = 0; e < 2; e++) {
            float l = lpart[mt][e];
            l += __shfl_xor_sync(0xffffffffu, l, 1);
            l += __shfl_xor_sync(0xffffffffu, l, 2);
            if (tg == 0) stat_l[wn*128 + wm*32 + mt*16 + g + 8*e] = l;
        }
    __syncthreads();
    if (tid < 128) fin_il[tid] = 1.0f / (stat_l[tid] + stat_l[128 + tid]);
    __syncthreads();

    float fil[2][2];
    #pragma unroll
    for (int mt = 0; mt < 2; mt++)
        #pragma unroll
        for (int e = 0; e < 2; e++)
            fil[mt][e] = fin_il[wm*32 + mt*16 + g + 8*e];

    // ----------------- Pass 2: attention write + A@V -----------------
    float av[2][4][4];
    #pragma unroll
    for (int mt = 0; mt < 2; mt++)
        #pragma unroll
        for (int nt = 0; nt < 4; nt++)
            #pragma unroll
            for (int j = 0; j < 4; j++) av[mt][nt][j] = 0.f;

    for (int kt = 0; kt < NTILE; kt++) {
        int cur = kt & 1;
        __half* Ksb = cur ? Kb1 : Kb0;
        __half* Vsb = cur ? Vb1 : Vb0;
        const int* mk = maskv + cur*64;

        if (kt + 1 < NTILE) {
            __half* Kn = cur ? Kb0 : Kb1;
            __half* Vn = cur ? Vb0 : Vb1;
            const __half* ksrc = Kg + (size_t)(kt+1)*64*64;
            const __half* vsrc = Vg + (size_t)(kt+1)*64*64;
            #pragma unroll
            for (int i = 0; i < 2; i++) {
                int id = tid + 256*i, r = id >> 3, c = (id & 7)*8;
                cpa16(sptr(&Kn[r*HST + c]), ksrc + r*64 + c);
                cpa16(sptr(&Vn[r*HST + c]), vsrc + r*64 + c);
            }
            if (tid < 64) cpa4(sptr(&maskv[(1-cur)*64 + tid]), mg + (kt+1)*64 + tid);
            cp_commit();
            cp_wait<1>();
        } else {
            cp_wait<0>();
        }
        __syncthreads();

        float sa[2][4][4];
        #pragma unroll
        for (int mt = 0; mt < 2; mt++)
            #pragma unroll
            for (int nt = 0; nt < 4; nt++)
                #pragma unroll
                for (int j = 0; j < 4; j++) sa[mt][nt][j] = 0.f;

        #pragma unroll
        for (int ks = 0; ks < 64; ks += 16) {
            uint32_t aF[2][4], bF[2][4];
            #pragma unroll
            for (int mt = 0; mt < 2; mt++)
                ldsm4(sptr(&Qs[(wm*32 + mt*16 + a_off_r)*HST + ks + a_off_c]), aF[mt]);
            #pragma unroll
            for (int ntp = 0; ntp < 2; ntp++)
                ldsm4(sptr(&Ksb[(wn*32 + ntp*16 + b_off_r)*HST + ks + b_off_c]), bF[ntp]);
            #pragma unroll
            for (int mt = 0; mt < 2; mt++)
                #pragma unroll
                for (int nt = 0; nt < 4; nt++)
                    mma16(sa[mt][nt], aF[mt][0], aF[mt][1], aF[mt][2], aF[mt][3],
                          bF[nt>>1][(nt&1)*2], bF[nt>>1][(nt&1)*2 + 1]);
        }

        #pragma unroll
        for (int nt = 0; nt < 4; nt++) {
            int c0 = wn*32 + nt*8 + 2*tg;
            int m0 = mk[c0], m1 = mk[c0 + 1];
            #pragma unroll
            for (int mt = 0; mt < 2; mt++) {
                #pragma unroll
                for (int e = 0; e < 2; e++) {
                    float p0 = m0 ? __expf(sa[mt][nt][2*e])   * fil[mt][e] : 0.f;
                    float p1 = m1 ? __expf(sa[mt][nt][2*e+1]) * fil[mt][e] : 0.f;
                    int qr = wm*32 + mt*16 + g + 8*e;
                    if (att) {
                        size_t qglob = (size_t)bh*Ss + qb*BQ + qr;
                        *(float2*)&att[qglob*Ss + kt*64 + c0] = make_float2(p0, p1);
                    }
                    sth2(&Ps[qr*HST + c0], p0, p1);
                }
            }
        }
        __syncthreads();

        #pragma unroll
        for (int ks = 0; ks < 64; ks += 16) {
            uint32_t aF[2][4], bF[2][4];
            #pragma unroll
            for (int mt = 0; mt < 2; mt++)
                ldsm4(sptr(&Ps[(wm*32 + mt*16 + a_off_r)*HST + ks + a_off_c]), aF[mt]);
            #pragma unroll
            for (int ntp = 0; ntp < 2; ntp++)
                ldsm4t(sptr(&Vsb[(ks + v_off_r)*HST + wn*32 + ntp*16 + v_off_c]), bF[ntp]);
            #pragma unroll
            for (int mt = 0; mt < 2; mt++)
                #pragma unroll
                for (int nt = 0; nt < 4; nt++)
                    mma16(av[mt][nt], aF[mt][0], aF[mt][1], aF[mt][2], aF[mt][3],
                          bF[nt>>1][(nt&1)*2], bF[nt>>1][(nt&1)*2 + 1]);
        }
        __syncthreads();
    }

    // ctx epilogue: ctx[b][s][h*64+dk] as half
    #pragma unroll
    for (int mt = 0; mt < 2; mt++) {
        #pragma unroll
        for (int nt = 0; nt < 4; nt++) {
            int dk = wn*32 + nt*8 + 2*tg;
            #pragma unroll
            for (int e = 0; e < 2; e++) {
                int srow = qb*BQ + wm*32 + mt*16 + g + 8*e;
                size_t idx = ((size_t)b*Ss + srow)*Dd + hd*DKk + dk;
                sth2(&g_ctx[idx], av[mt][nt][2*e], av[mt][nt][2*e+1]);
            }
        }
    }
}

// ---------------------------------------------------------------------------

extern "C" void kernel_launch(void* const* d_in, const int* in_sizes, int n_in,
                              void* d_out, int out_size)
{
    const float* q    = (const float*)d_in[0];
    const float* k    = (const float*)d_in[1];
    const float* v    = (const float*)d_in[2];
    const int*   mask = (const int*)  d_in[3];
    const float* wq_w = (const float*)d_in[4];
    const float* wq_b = (const float*)d_in[5];
    const float* wk_w = (const float*)d_in[6];
    const float* wk_b = (const float*)d_in[7];
    const float* wv_w = (const float*)d_in[8];
    const float* wv_b = (const float*)d_in[9];
    const float* wo_w = (const float*)d_in[10];
    const float* wo_b = (const float*)d_in[11];

    float* out = (float*)d_out;
    float* att = nullptr;
    long long need = (long long)Bb*Ss*Dd + (long long)Bb*Hh*Ss*Ss;
    if ((long long)out_size >= need) att = out + (size_t)Bb*Ss*Dd;

    const int attn_smem = (BQ*HST*2 + 4*64*HST) * 2 + (256 + 128) * 4 + 2*64*4;
    cudaFuncSetAttribute(attn_kernel, cudaFuncAttributeMaxDynamicSharedMemorySize,
                         attn_smem);

    dim3 gqkv(Dd/128, Mm/128, 3);
    gemm_qkv<<<gqkv, 256>>>(q, k, v, wq_w, wk_w, wv_w, wq_b, wk_b, wv_b);

    attn_kernel<<<dim3(Ss/BQ, Bb*Hh), 256, attn_smem>>>(mask, att);

    gemm_o<<<dim3(Dd/128, Mm/128), 256>>>(wo_w, wo_b, out);
}

// round 8
// speedup vs baseline: 2.6635x; 1.2330x over previous
#include <cuda_runtime.h>
#include <cuda_fp16.h>
#include <cstdint>

#define Bb 2
#define Ss 2048
#define Dd 1024
#define Hh 16
#define DKk 64
#define Mm (Bb*Ss)
#define NTILE (Ss/64)

// Scratch (allocation-free rule: __device__ globals). fp16 internal datapath.
__device__ __half g_Xh[(size_t)3*Mm*Dd];       // converted q,k,v inputs
__device__ __half g_Wh[(size_t)4*Dd*Dd];       // converted wq,wk,wv,wo
__device__ __half g_Qh[(size_t)Bb*Hh*Ss*DKk];  // holds Qh * 0.125 * log2(e)
__device__ __half g_Kh[(size_t)Bb*Hh*Ss*DKk];
__device__ __half g_Vh[(size_t)Bb*Hh*Ss*DKk];
__device__ __half g_ctx[(size_t)Bb*Ss*Dd];

// ---------------- PTX helpers ----------------
__device__ __forceinline__ uint32_t sptr(const void* p){
    return (uint32_t)__cvta_generic_to_shared(p);
}
__device__ __forceinline__ void cpa16(uint32_t s, const void* g){
    asm volatile("cp.async.ca.shared.global [%0], [%1], 16;\n" :: "r"(s), "l"(g));
}
__device__ __forceinline__ void cpa4(uint32_t s, const void* g){
    asm volatile("cp.async.ca.shared.global [%0], [%1], 4;\n" :: "r"(s), "l"(g));
}
__device__ __forceinline__ void cp_commit(){ asm volatile("cp.async.commit_group;\n"); }
template<int N> __device__ __forceinline__ void cp_wait(){
    asm volatile("cp.async.wait_group %0;\n" :: "n"(N));
}

__device__ __forceinline__ void ldsm4(uint32_t a, uint32_t* r){
    asm volatile("ldmatrix.sync.aligned.m8n8.x4.shared.b16 {%0,%1,%2,%3},[%4];\n"
        : "=r"(r[0]), "=r"(r[1]), "=r"(r[2]), "=r"(r[3]) : "r"(a));
}
__device__ __forceinline__ void ldsm4t(uint32_t a, uint32_t* r){
    asm volatile("ldmatrix.sync.aligned.m8n8.x4.trans.shared.b16 {%0,%1,%2,%3},[%4];\n"
        : "=r"(r[0]), "=r"(r[1]), "=r"(r[2]), "=r"(r[3]) : "r"(a));
}

__device__ __forceinline__ void mma16(float* c,
    uint32_t a0, uint32_t a1, uint32_t a2, uint32_t a3, uint32_t b0, uint32_t b1)
{
    asm volatile(
      "mma.sync.aligned.m16n8k16.row.col.f32.f16.f16.f32 "
      "{%0,%1,%2,%3},{%4,%5,%6,%7},{%8,%9},{%0,%1,%2,%3};\n"
      : "+f"(c[0]), "+f"(c[1]), "+f"(c[2]), "+f"(c[3])
      : "r"(a0), "r"(a1), "r"(a2), "r"(a3), "r"(b0), "r"(b1));
}

__device__ __forceinline__ void sth2(__half* p, float lo, float hi){
    *(__half2*)p = __floats2half2_rn(lo, hi);
}
__device__ __forceinline__ uint32_t packh2(float lo, float hi){
    __half2 h = __floats2half2_rn(lo, hi);
    return *(uint32_t*)&h;
}
__device__ __forceinline__ float ex2(float x){
    float y; asm("ex2.approx.ftz.f32 %0, %1;" : "=f"(y) : "f"(x)); return y;
}

// head-layout index: m=(b*S+s), n=(h*64+dk) -> [b][h][s][dk]
__device__ __forceinline__ size_t hidx(int m, int n){
    int b = m >> 11;
    int s = m & 2047;
    int h = n >> 6;
    int dk = n & 63;
    return (((size_t)b*Hh + h)*Ss + s)*DKk + dk;
}

// ---------------------------------------------------------------------------
// Convert q,k,v (3 x 2^22 elems) and 4 weights (4 x 2^20) fp32 -> fp16.
// One thread per float4 (2^22 total).
// ---------------------------------------------------------------------------
__global__ void __launch_bounds__(256)
convert_all(const float* __restrict__ q, const float* __restrict__ k,
            const float* __restrict__ v,
            const float* __restrict__ wq, const float* __restrict__ wk,
            const float* __restrict__ wv, const float* __restrict__ wo)
{
    size_t t = (size_t)blockIdx.x*256 + threadIdx.x;
    const float* src; __half* dst; size_t off;
    if (t < ((size_t)3<<20)) {
        int which = (int)(t >> 20);
        off = t & 0xFFFFFu;
        src = (which == 0) ? q : (which == 1) ? k : v;
        dst = g_Xh + ((size_t)which << 22);
    } else {
        size_t t2 = t - ((size_t)3<<20);
        int which = (int)(t2 >> 18);
        off = t2 & 0x3FFFFu;
        src = (which == 0) ? wq : (which == 1) ? wk : (which == 2) ? wv : wo;
        dst = g_Wh + ((size_t)which << 20);
    }
    float4 vv = ((const float4*)src)[off];
    __half2 h0 = __floats2half2_rn(vv.x, vv.y);
    __half2 h1 = __floats2half2_rn(vv.z, vv.w);
    uint2 u; u.x = *(uint32_t*)&h0; u.y = *(uint32_t*)&h1;
    ((uint2*)dst)[off] = u;
}

// ---------------------------------------------------------------------------
// All-half projection GEMM: C[4096,1024] = X @ W^T + bias, cp.async 2-stage.
// Block 128x128, BK=32, 8 warps (2m x 4n), warp 64x32.
// ---------------------------------------------------------------------------
#define GST 40   // smem row stride in halves (80B, 16B-aligned, LDSM conflict-free)

template<bool HEADOUT>
__device__ __forceinline__ void gemm_body(const __half* __restrict__ X,
                                          const __half* __restrict__ W,
                                          const float* __restrict__ bias,
                                          void* __restrict__ opv,
                                          float oscale)
{
    __shared__ __half As[2][128*GST];
    __shared__ __half Bs[2][128*GST];

    const int tid = threadIdx.x;
    const int lane = tid & 31, w = tid >> 5;
    const int wm = w >> 2, wn = w & 3;
    const int g = lane >> 2, tg = lane & 3;
    const int by = blockIdx.y, bx = blockIdx.x;

    const int a_off_r = (lane & 7) + ((lane >> 3) & 1) * 8;
    const int a_off_c = (lane >> 4) << 3;
    const int b_off_r = (lane & 7) + ((lane >> 4) << 3);
    const int b_off_c = ((lane >> 3) & 1) << 3;

    const __half* xblk = X + (size_t)(by*128) * Dd;
    const __half* wblk = W + (size_t)(bx*128) * Dd;

    const int ldr = tid >> 2;            // 0..63
    const int ldc = (tid & 3) * 8;       // 0,8,16,24

    float acc[4][4][4];
    #pragma unroll
    for (int mt = 0; mt < 4; mt++)
        #pragma unroll
        for (int nt = 0; nt < 4; nt++)
            #pragma unroll
            for (int j = 0; j < 4; j++) acc[mt][nt][j] = 0.f;

    // tile loader: stage st <- k-tile kt
    auto load_tile = [&](int kt, int st){
        const __half* xs = xblk + kt*32;
        const __half* ws = wblk + kt*32;
        #pragma unroll
        for (int i = 0; i < 2; i++) {
            int r = ldr + 64*i;
            cpa16(sptr(&As[st][r*GST + ldc]), xs + (size_t)r*Dd + ldc);
            cpa16(sptr(&Bs[st][r*GST + ldc]), ws + (size_t)r*Dd + ldc);
        }
    };

    load_tile(0, 0); cp_commit();

    for (int kt = 0; kt < Dd/32; kt++) {
        int cur = kt & 1;
        if (kt + 1 < Dd/32) {
            load_tile(kt + 1, 1 - cur); cp_commit();
            cp_wait<1>();
        } else {
            cp_wait<0>();
        }
        __syncthreads();

        #pragma unroll
        for (int ks = 0; ks < 32; ks += 16) {
            uint32_t aF[4][4], bF[2][4];
            #pragma unroll
            for (int mt = 0; mt < 4; mt++)
                ldsm4(sptr(&As[cur][(wm*64 + mt*16 + a_off_r)*GST + ks + a_off_c]), aF[mt]);
            #pragma unroll
            for (int ntp = 0; ntp < 2; ntp++)
                ldsm4(sptr(&Bs[cur][(wn*32 + ntp*16 + b_off_r)*GST + ks + b_off_c]), bF[ntp]);
            #pragma unroll
            for (int mt = 0; mt < 4; mt++)
                #pragma unroll
                for (int nt = 0; nt < 4; nt++)
                    mma16(acc[mt][nt], aF[mt][0], aF[mt][1], aF[mt][2], aF[mt][3],
                          bF[nt>>1][(nt&1)*2], bF[nt>>1][(nt&1)*2 + 1]);
        }
        __syncthreads();
    }

    #pragma unroll
    for (int mt = 0; mt < 4; mt++) {
        int m0 = by*128 + wm*64 + mt*16 + g;
        #pragma unroll
        for (int nt = 0; nt < 4; nt++) {
            int n0 = bx*128 + wn*32 + nt*8 + tg*2;
            float bv0 = bias[n0], bv1 = bias[n0 + 1];
            if (HEADOUT) {
                __half* op = (__half*)opv;
                sth2(&op[hidx(m0,     n0)], (acc[mt][nt][0] + bv0) * oscale,
                                            (acc[mt][nt][1] + bv1) * oscale);
                sth2(&op[hidx(m0 + 8, n0)], (acc[mt][nt][2] + bv0) * oscale,
                                            (acc[mt][nt][3] + bv1) * oscale);
            } else {
                float* op = (float*)opv;
                *(float2*)&op[(size_t)m0*Dd + n0] =
                    make_float2(acc[mt][nt][0] + bv0, acc[mt][nt][1] + bv1);
                *(float2*)&op[(size_t)(m0+8)*Dd + n0] =
                    make_float2(acc[mt][nt][2] + bv0, acc[mt][nt][3] + bv1);
            }
        }
    }
}

__global__ void __launch_bounds__(256, 2)
gemm_qkv(const float* __restrict__ bq, const float* __restrict__ bk,
         const float* __restrict__ bv)
{
    int mode = blockIdx.z;
    const __half* X = g_Xh + ((size_t)mode << 22);
    const __half* W = g_Wh + ((size_t)mode << 20);
    const float* B = (mode == 0) ? bq : (mode == 1) ? bk : bv;
    __half* op = (mode == 0) ? g_Qh : (mode == 1) ? g_Kh : g_Vh;
    // fold 1/sqrt(Dk) * log2(e) into Q so softmax uses raw ex2
    float sc = (mode == 0) ? 0.125f * 1.4426950408889634f : 1.0f;
    gemm_body<true>(X, W, B, op, sc);
}

__global__ void __launch_bounds__(256, 2)
gemm_o(const float* __restrict__ bias, float* __restrict__ outp)
{
    gemm_body<false>(g_ctx, g_Wh + ((size_t)3 << 20), bias, outp, 1.0f);
}

// ---------------------------------------------------------------------------
// Attention. q-tile = 128 rows, 8 warps, each warp = 16 q-rows x FULL 64 cols.
// Q fragments hoisted to registers. Pass 1: sumexp only (scores are base-2).
// Pass 2: recompute scores, write normalized fp32 attention, AV mma with
// P kept entirely in registers (score C-frags == AV A-frags layout).
// ---------------------------------------------------------------------------
#define HST 72
#define BQ 128

__global__ void __launch_bounds__(256, 2)
attn_kernel(const int* __restrict__ mask, float* __restrict__ att)
{
    extern __shared__ __half smh[];
    __half* Qs  = smh;                  // 128*HST
    __half* Kb0 = Qs  + BQ*HST;         // 64*HST
    __half* Kb1 = Kb0 + 64*HST;
    __half* Vb0 = Kb1 + 64*HST;
    __half* Vb1 = Vb0 + 64*HST;
    int*   maskv = (int*)(Vb1 + 64*HST);   // 2*64

    const int tid = threadIdx.x;
    const int lane = tid & 31, w = tid >> 5;     // warp owns rows w*16..w*16+15
    const int g = lane >> 2, tg = lane & 3;
    const int qb = blockIdx.x, bh = blockIdx.y;
    const int b = bh >> 4, hd = bh & 15;

    const int a_off_r = (lane & 7) + ((lane >> 3) & 1) * 8;
    const int a_off_c = (lane >> 4) << 3;
    const int b_off_r = (lane & 7) + ((lane >> 4) << 3);
    const int b_off_c = ((lane >> 3) & 1) << 3;
    const int v_off_r = (lane & 7) + (((lane >> 3) & 1) << 3);
    const int v_off_c = (lane >> 4) << 3;

    const __half* Qg = g_Qh + ((size_t)bh*Ss + qb*BQ) * DKk;
    const __half* Kg = g_Kh + (size_t)bh*Ss*DKk;
    const __half* Vg = g_Vh + (size_t)bh*Ss*DKk;
    const int*    mg = mask + b*Ss;

    // prologue: Q tile + K tile 0 + mask 0
    #pragma unroll
    for (int i = 0; i < 4; i++) {
        int id = tid + 256*i, r = id >> 3, c = (id & 7)*8;
        cpa16(sptr(&Qs[r*HST + c]), Qg + r*64 + c);
    }
    #pragma unroll
    for (int i = 0; i < 2; i++) {
        int id = tid + 256*i, r = id >> 3, c = (id & 7)*8;
        cpa16(sptr(&Kb0[r*HST + c]), Kg + r*64 + c);
    }
    if (tid < 64) cpa4(sptr(&maskv[tid]), mg + tid);
    cp_commit();
    cp_wait<0>();
    __syncthreads();

    // Q fragments once (16 rows x 64 cols per warp)
    uint32_t qF[4][4];
    #pragma unroll
    for (int ksi = 0; ksi < 4; ksi++)
        ldsm4(sptr(&Qs[(w*16 + a_off_r)*HST + ksi*16 + a_off_c]), qF[ksi]);

    // ----------------- Pass 1: row sumexp -----------------
    float lp[2] = {0.f, 0.f};

    for (int kt = 0; kt < NTILE; kt++) {
        int cur = kt & 1;
        __half* Ksb = cur ? Kb1 : Kb0;
        const int* mk = maskv + cur*64;

        if (kt + 1 < NTILE) {
            __half* Kn = cur ? Kb0 : Kb1;
            const __half* src = Kg + (size_t)(kt+1)*64*64;
            #pragma unroll
            for (int i = 0; i < 2; i++) {
                int id = tid + 256*i, r = id >> 3, c = (id & 7)*8;
                cpa16(sptr(&Kn[r*HST + c]), src + r*64 + c);
            }
            if (tid < 64) cpa4(sptr(&maskv[(1-cur)*64 + tid]), mg + (kt+1)*64 + tid);
            cp_commit();
            cp_wait<1>();
        } else {
            cp_wait<0>();
        }
        __syncthreads();

        float sa[8][4];
        #pragma unroll
        for (int nt = 0; nt < 8; nt++)
            #pragma unroll
            for (int j = 0; j < 4; j++) sa[nt][j] = 0.f;

        #pragma unroll
        for (int ksi = 0; ksi < 4; ksi++) {
            uint32_t bF[4][4];
            #pragma unroll
            for (int np = 0; np < 4; np++)
                ldsm4(sptr(&Ksb[(np*16 + b_off_r)*HST + ksi*16 + b_off_c]), bF[np]);
            #pragma unroll
            for (int nt = 0; nt < 8; nt++)
                mma16(sa[nt], qF[ksi][0], qF[ksi][1], qF[ksi][2], qF[ksi][3],
                      bF[nt>>1][(nt&1)*2], bF[nt>>1][(nt&1)*2 + 1]);
        }

        #pragma unroll
        for (int nt = 0; nt < 8; nt++) {
            int c0 = nt*8 + 2*tg;
            int m0 = mk[c0], m1 = mk[c0 + 1];
            float s0 = m0 ? sa[nt][0] : -1e9f;
            float s1 = m1 ? sa[nt][1] : -1e9f;
            float s2 = m0 ? sa[nt][2] : -1e9f;
            float s3 = m1 ? sa[nt][3] : -1e9f;
            lp[0] += ex2(s0) + ex2(s1);
            lp[1] += ex2(s2) + ex2(s3);
        }
        __syncthreads();
    }

    // reduce over tg lanes only (warp owns full rows)
    float fil[2];
    #pragma unroll
    for (int e = 0; e < 2; e++) {
        float l = lp[e];
        l += __shfl_xor_sync(0xffffffffu, l, 1);
        l += __shfl_xor_sync(0xffffffffu, l, 2);
        fil[e] = 1.0f / l;
    }

    // issue pass-2 tile 0 (K+V+mask)
    #pragma unroll
    for (int i = 0; i < 2; i++) {
        int id = tid + 256*i, r = id >> 3, c = (id & 7)*8;
        cpa16(sptr(&Kb0[r*HST + c]), Kg + r*64 + c);
        cpa16(sptr(&Vb0[r*HST + c]), Vg + r*64 + c);
    }
    if (tid < 64) cpa4(sptr(&maskv[tid]), mg + tid);
    cp_commit();

    // ----------------- Pass 2: attention write + A@V -----------------
    float av[8][4];
    #pragma unroll
    for (int nt = 0; nt < 8; nt++)
        #pragma unroll
        for (int j = 0; j < 4; j++) av[nt][j] = 0.f;

    const int row0 = qb*BQ + w*16 + g;
    float* attr0 = att ? att + ((size_t)bh*Ss + row0)*Ss : nullptr;
    float* attr1 = att ? attr0 + 8*Ss : nullptr;

    for (int kt = 0; kt < NTILE; kt++) {
        int cur = kt & 1;
        __half* Ksb = cur ? Kb1 : Kb0;
        __half* Vsb = cur ? Vb1 : Vb0;
        const int* mk = maskv + cur*64;

        if (kt + 1 < NTILE) {
            __half* Kn = cur ? Kb0 : Kb1;
            __half* Vn = cur ? Vb0 : Vb1;
            const __half* ksrc = Kg + (size_t)(kt+1)*64*64;
            const __half* vsrc = Vg + (size_t)(kt+1)*64*64;
            #pragma unroll
            for (int i = 0; i < 2; i++) {
                int id = tid + 256*i, r = id >> 3, c = (id & 7)*8;
                cpa16(sptr(&Kn[r*HST + c]), ksrc + r*64 + c);
                cpa16(sptr(&Vn[r*HST + c]), vsrc + r*64 + c);
            }
            if (tid < 64) cpa4(sptr(&maskv[(1-cur)*64 + tid]), mg + (kt+1)*64 + tid);
            cp_commit();
            cp_wait<1>();
        } else {
            cp_wait<0>();
        }
        __syncthreads();

        float sa[8][4];
        #pragma unroll
        for (int nt = 0; nt < 8; nt++)
            #pragma unroll
            for (int j = 0; j < 4; j++) sa[nt][j] = 0.f;

        #pragma unroll
        for (int ksi = 0; ksi < 4; ksi++) {
            uint32_t bF[4][4];
            #pragma unroll
            for (int np = 0; np < 4; np++)
                ldsm4(sptr(&Ksb[(np*16 + b_off_r)*HST + ksi*16 + b_off_c]), bF[np]);
            #pragma unroll
            for (int nt = 0; nt < 8; nt++)
                mma16(sa[nt], qF[ksi][0], qF[ksi][1], qF[ksi][2], qF[ksi][3],
                      bF[nt>>1][(nt&1)*2], bF[nt>>1][(nt&1)*2 + 1]);
        }

        // softmax values: overwrite sa with p, write fp32 attention
        #pragma unroll
        for (int nt = 0; nt < 8; nt++) {
            int c0 = nt*8 + 2*tg;
            int m0 = mk[c0], m1 = mk[c0 + 1];
            float p0 = m0 ? ex2(sa[nt][0]) * fil[0] : 0.f;
            float p1 = m1 ? ex2(sa[nt][1]) * fil[0] : 0.f;
            float p2 = m0 ? ex2(sa[nt][2]) * fil[1] : 0.f;
            float p3 = m1 ? ex2(sa[nt][3]) * fil[1] : 0.f;
            if (att) {
                *(float2*)&attr0[kt*64 + c0] = make_float2(p0, p1);
                *(float2*)&attr1[kt*64 + c0] = make_float2(p2, p3);
            }
            sa[nt][0] = p0; sa[nt][1] = p1; sa[nt][2] = p2; sa[nt][3] = p3;
        }

        // AV: A-frags straight from registers, B-frags via ldmatrix.trans on V
        #pragma unroll
        for (int ksi = 0; ksi < 4; ksi++) {
            uint32_t ap0 = packh2(sa[2*ksi][0],   sa[2*ksi][1]);
            uint32_t ap1 = packh2(sa[2*ksi][2],   sa[2*ksi][3]);
            uint32_t ap2 = packh2(sa[2*ksi+1][0], sa[2*ksi+1][1]);
            uint32_t ap3 = packh2(sa[2*ksi+1][2], sa[2*ksi+1][3]);
            uint32_t bV[4][4];
            #pragma unroll
            for (int np = 0; np < 4; np++)
                ldsm4t(sptr(&Vsb[(ksi*16 + v_off_r)*HST + np*16 + v_off_c]), bV[np]);
            #pragma unroll
            for (int nt = 0; nt < 8; nt++)
                mma16(av[nt], ap0, ap1, ap2, ap3,
                      bV[nt>>1][(nt&1)*2], bV[nt>>1][(nt&1)*2 + 1]);
        }
        __syncthreads();
    }

    // ctx epilogue: ctx[b][s][h*64+dk] as half
    #pragma unroll
    for (int nt = 0; nt < 8; nt++) {
        int dk = nt*8 + 2*tg;
        size_t i0 = ((size_t)b*Ss + row0)*Dd + hd*DKk + dk;
        sth2(&g_ctx[i0],          av[nt][0], av[nt][1]);
        sth2(&g_ctx[i0 + 8*Dd],   av[nt][2], av[nt][3]);
    }
}

// ---------------------------------------------------------------------------

extern "C" void kernel_launch(void* const* d_in, const int* in_sizes, int n_in,
                              void* d_out, int out_size)
{
    const float* q    = (const float*)d_in[0];
    const float* k    = (const float*)d_in[1];
    const float* v    = (const float*)d_in[2];
    const int*   mask = (const int*)  d_in[3];
    const float* wq_w = (const float*)d_in[4];
    const float* wq_b = (const float*)d_in[5];
    const float* wk_w = (const float*)d_in[6];
    const float* wk_b = (const float*)d_in[7];
    const float* wv_w = (const float*)d_in[8];
    const float* wv_b = (const float*)d_in[9];
    const float* wo_w = (const float*)d_in[10];
    const float* wo_b = (const float*)d_in[11];

    float* out = (float*)d_out;
    float* att = nullptr;
    long long need = (long long)Bb*Ss*Dd + (long long)Bb*Hh*Ss*Ss;
    if ((long long)out_size >= need) att = out + (size_t)Bb*Ss*Dd;

    const int attn_smem = (BQ*HST + 4*64*HST) * 2 + 2*64*4;
    cudaFuncSetAttribute(attn_kernel, cudaFuncAttributeMaxDynamicSharedMemorySize,
                         attn_smem);

    convert_all<<<16384, 256>>>(q, k, v, wq_w, wk_w, wv_w, wo_w);

    gemm_qkv<<<dim3(Dd/128, Mm/128, 3), 256>>>(wq_b, wk_b, wv_b);

    attn_kernel<<<dim3(Ss/BQ, Bb*Hh), 256, attn_smem>>>(mask, att);

    gemm_o<<<dim3(Dd/128, Mm/128), 256>>>(wo_b, out);
}